// round 11
// baseline (speedup 1.0000x reference)
#include <cuda_runtime.h>
#include <cuda_fp16.h>
#include <cstdint>
#include <cstring>

#define KCODES 1024
#define CD     64
#define NPIX   131072
#define HWDIM  4096
#define TPB    256
#define LOSS_OFF 8388608
#define IDX_OFF  8388609
#define NCHUNK 16            // 16 chunks x 64 codes
#define TPC    8             // tiles (of 8 codes) per chunk
#define EPS    0.35f
#define NCAND  16
#define SOFF   128.0f        // score offset making packed keys positive

__device__ float g_halfnorm[KCODES];
__device__ float g_loss;
__device__ int   g_done = 0;
// fragment-ordered fp16 codebook: [tile(128)][lane(32)][2 x uint4]
__device__ __align__(16) uint4 g_Bh[128 * 32 * 2];

static __device__ __forceinline__ uint32_t smem_u32(const void* p) {
    uint32_t a;
    asm("{ .reg .u64 t; cvta.to.shared.u64 t, %1; cvt.u32.u64 %0, t; }" : "=r"(a) : "l"(p));
    return a;
}
static __device__ __forceinline__ void cp_async16(uint32_t s, const void* g) {
    asm volatile("cp.async.ca.shared.global [%0], [%1], 16;" :: "r"(s), "l"(g) : "memory");
}
static __device__ __forceinline__ uint32_t hpack(float a, float b) {
    __half2 h = __floats2half2_rn(a, b);
    uint32_t u; memcpy(&u, &h, 4); return u;
}

#define MMA(d, a, bx, by)                                                          \
    asm volatile("mma.sync.aligned.m16n8k16.row.col.f32.f16.f16.f32 "              \
        "{%0,%1,%2,%3},{%4,%5,%6,%7},{%8,%9},{%0,%1,%2,%3};"                       \
        : "+f"(d[0]), "+f"(d[1]), "+f"(d[2]), "+f"(d[3])                           \
        : "r"(a[0]), "r"(a[1]), "r"(a[2]), "r"(a[3]), "r"(bx), "r"(by))

// cheap per-score path: pack key, fold into per-group running min (2 ALU ops)
#define PACKMIN(cm, v, n)                                                          \
    { uint32_t _k = (__float_as_uint(v) & 0xFFFFFC00u) | (uint32_t)(n);            \
      cm = min(cm, _k); }

// branch-free insert into sorted-4 (rare: 2x per chunk per slot)
#define INS4(p, kin)                                                               \
    { uint32_t _a, _b = (kin);                                                     \
      _a = min(t1[p], _b); _b = max(t1[p], _b); t1[p] = _a;                        \
      _a = min(t2[p], _b); _b = max(t2[p], _b); t2[p] = _a;                        \
      _a = min(t3[p], _b); _b = max(t3[p], _b); t3[p] = _a;                        \
      t4[p] = min(t4[p], _b); }

// ---- prep: halfnorms (R1-replica arithmetic) + fragment-ordered fp16 codebook --
__global__ void vq_prep(const float* __restrict__ emb) {
    int t = blockIdx.x * blockDim.x + threadIdx.x;   // 4096 threads
    if (t == 0) g_loss = 0.f;
    if (t < KCODES) {
        const float4* row = (const float4*)(emb + (size_t)t * CD);
        float s = 0.f;
#pragma unroll
        for (int i = 0; i < CD / 4; i++) {
            float4 v = row[i];
            s += v.x * v.x + v.y * v.y + v.z * v.z + v.w * v.w;
        }
        g_halfnorm[t] = 0.5f * s;
    }
    int tile = t >> 5, l = t & 31, m = l & 3;
    int code = tile * 8 + (l >> 2);
    const float* e = emb + (size_t)code * CD;
    uint32_t h[8];
#pragma unroll
    for (int s = 0; s < 4; s++) {
        int c0 = 16 * s + 2 * m;
        h[2 * s]     = hpack(e[c0],     e[c0 + 1]);
        h[2 * s + 1] = hpack(e[c0 + 8], e[c0 + 9]);
    }
    int base = (tile * 32 + l) * 2;
    g_Bh[base]     = make_uint4(h[0], h[1], h[2], h[3]);
    g_Bh[base + 1] = make_uint4(h[4], h[5], h[6], h[7]);
}

// ---- main: fp16 HMMA screen + group-min selection + exact group rescue ----
__global__ __launch_bounds__(TPB, 2)
void vq_mma(const float* __restrict__ x, const float* __restrict__ emb,
            float* __restrict__ out, int out_size)
{
    // 32 KB pool: B double-buffer (2 x 8 KB) during loop; candidate keys after
    __shared__ __align__(16) unsigned char s_pool[32768];
    __shared__ float s_hn[KCODES];      // exact (rescue comparator)
    __shared__ float s_hnOff[KCODES];   // hn + SOFF (accumulator init)
    __shared__ float s_red[8];

    const int tid = threadIdx.x;
    const int w = tid >> 5, l = tid & 31, g = l >> 2, m = l & 3;
    const int blockpix = blockIdx.x << 8;
    const int b = blockpix >> 12;
    const int hwbase = (blockpix & (HWDIM - 1)) + (w << 5);
    const float* xb = x + (size_t)b * CD * HWDIM;

    // ---- build A fragments (negated z, fp16) ----
    uint32_t ah[2][4][4];
#pragma unroll
    for (int ri = 0; ri < 4; ri++) {
        const int mt = ri >> 1, rr = ri & 1;
        const float* xp = xb + hwbase + g + rr * 8 + mt * 16;
#pragma unroll
        for (int s = 0; s < 4; s++) {
            int c0 = 16 * s + 2 * m;
            float f0 = -__ldg(xp + (size_t)c0 * HWDIM);
            float f1 = -__ldg(xp + (size_t)(c0 + 1) * HWDIM);
            float f2 = -__ldg(xp + (size_t)(c0 + 8) * HWDIM);
            float f3 = -__ldg(xp + (size_t)(c0 + 9) * HWDIM);
            ah[mt][s][rr]     = hpack(f0, f1);
            ah[mt][s][2 + rr] = hpack(f2, f3);
        }
    }

    // halfnorms to smem (exact + offset copy)
#pragma unroll
    for (int i = 0; i < 4; i++) {
        float h = g_halfnorm[tid + i * TPB];
        s_hn[tid + i * TPB]    = h;
        s_hnOff[tid + i * TPB] = h + SOFF;
    }

    // prefetch chunk 0 (8 KB: 2 uint4 per thread)
    {
        uint32_t dh = smem_u32(s_pool) + tid * 32;
        const uint4* sh = g_Bh + tid * 2;
        cp_async16(dh, sh); cp_async16(dh + 16, sh + 1);
        asm volatile("cp.async.commit_group;" ::: "memory");
    }
    asm volatile("cp.async.wait_group 0;" ::: "memory");
    __syncthreads();

    uint32_t t1[4] = {0xFFFFFFFFu,0xFFFFFFFFu,0xFFFFFFFFu,0xFFFFFFFFu};
    uint32_t t2[4] = {0xFFFFFFFFu,0xFFFFFFFFu,0xFFFFFFFFu,0xFFFFFFFFu};
    uint32_t t3[4] = {0xFFFFFFFFu,0xFFFFFFFFu,0xFFFFFFFFu,0xFFFFFFFFu};
    uint32_t t4[4] = {0xFFFFFFFFu,0xFFFFFFFFu,0xFFFFFFFFu,0xFFFFFFFFu};

#pragma unroll 1
    for (int ch = 0; ch < NCHUNK; ch++) {
        const int buf = ch & 1;
        if (ch + 1 < NCHUNK) {   // async prefetch next chunk
            uint32_t dh = smem_u32(s_pool) + (buf ^ 1) * 8192 + tid * 32;
            const uint4* sh = g_Bh + (ch + 1) * 512 + tid * 2;
            cp_async16(dh, sh); cp_async16(dh + 16, sh + 1);
            asm volatile("cp.async.commit_group;" ::: "memory");
        }

        // per-group running minima (group = 4 tiles x lane = 8 codes)
        uint32_t cm[2][4] = {{0xFFFFFFFFu,0xFFFFFFFFu,0xFFFFFFFFu,0xFFFFFFFFu},
                             {0xFFFFFFFFu,0xFFFFFFFFu,0xFFFFFFFFu,0xFFFFFFFFu}};

        const uint4* bhp = (const uint4*)(s_pool + buf * 8192);
#pragma unroll
        for (int t = 0; t < TPC; t++) {
            uint4 h0 = bhp[t * 64 + l * 2];
            uint4 h1 = bhp[t * 64 + l * 2 + 1];
            const int n0 = ch * 64 + t * 8 + 2 * m;
            float2 hp = *(const float2*)&s_hnOff[n0];
            const int gi = t >> 2;   // static under unroll

            float d0[4], d1[4];
            d0[0] = hp.x; d0[1] = hp.y; d0[2] = hp.x; d0[3] = hp.y;
            d1[0] = hp.x; d1[1] = hp.y; d1[2] = hp.x; d1[3] = hp.y;

            MMA(d0, ah[0][0], h0.x, h0.y); MMA(d1, ah[1][0], h0.x, h0.y);
            MMA(d0, ah[0][1], h0.z, h0.w); MMA(d1, ah[1][1], h0.z, h0.w);
            MMA(d0, ah[0][2], h1.x, h1.y); MMA(d1, ah[1][2], h1.x, h1.y);
            MMA(d0, ah[0][3], h1.z, h1.w); MMA(d1, ah[1][3], h1.z, h1.w);

            PACKMIN(cm[gi][0], d0[0], n0); PACKMIN(cm[gi][0], d0[1], n0 + 1);
            PACKMIN(cm[gi][1], d0[2], n0); PACKMIN(cm[gi][1], d0[3], n0 + 1);
            PACKMIN(cm[gi][2], d1[0], n0); PACKMIN(cm[gi][2], d1[1], n0 + 1);
            PACKMIN(cm[gi][3], d1[2], n0); PACKMIN(cm[gi][3], d1[3], n0 + 1);
        }
        // fold the chunk's 2 group-minima per slot into the lane's top-4
#pragma unroll
        for (int p = 0; p < 4; p++) { INS4(p, cm[0][p]); INS4(p, cm[1][p]); }

        asm volatile("cp.async.wait_group 0;" ::: "memory");
        __syncthreads();
    }

    // ---- dump all 16 per-pixel candidate keys (4 lanes x top-4 group-minima) --
    uint32_t (*s_keys)[NCAND] = (uint32_t(*)[NCAND])s_pool;   // 16 KB
#pragma unroll
    for (int p = 0; p < 4; p++) {
        int row = g + (p & 1) * 8 + (p >> 1) * 16;
        int pr = w * 32 + row;
        s_keys[pr][4 * m]     = t1[p];
        s_keys[pr][4 * m + 1] = t2[p];
        s_keys[pr][4 * m + 2] = t3[p];
        s_keys[pr][4 * m + 3] = t4[p];
    }
    __syncthreads();

    // ---- per-pixel exact group rescue (R1-replica comparator) ----
    const int pixel = blockpix + tid;
    const int hw = pixel & (HWDIM - 1);
    const float* xp = xb + hw;
    float z[CD];
#pragma unroll
    for (int c = 0; c < CD; c++) z[c] = __ldg(xp + (size_t)c * HWDIM);

    uint32_t key[NCAND];
#pragma unroll
    for (int i = 0; i < NCAND; i++) key[i] = s_keys[tid][i];

    uint32_t kmin = key[0];
#pragma unroll
    for (int i = 1; i < NCAND; i++) kmin = min(kmin, key[i]);
    const float lim = __uint_as_float(kmin & 0xFFFFFC00u) + EPS;

    float be = 3.4e38f; int bw = 0x7fffffff;
#pragma unroll 1
    for (int i = 0; i < NCAND; i++) {
        if (__uint_as_float(key[i] & 0xFFFFFC00u) <= lim) {
            // rescore this key's full 8-code group exactly
            int n  = key[i] & 1023;
            int gb = (n & ~63) + ((n >> 3) & 4) * 8 + (n & 6);
#pragma unroll 1
            for (int u = 0; u < 4; u++) {
#pragma unroll
                for (int e = 0; e < 2; e++) {
                    int ci = gb + u * 8 + e;
                    const float* er = emb + (size_t)ci * CD;
                    float p0 = 0.f, p1 = 0.f, p2 = 0.f, p3 = 0.f;
#pragma unroll
                    for (int q = 0; q < CD / 4; q++) {
                        p0 = fmaf(z[4*q],     er[4*q],     p0);
                        p1 = fmaf(z[4*q + 1], er[4*q + 1], p1);
                        p2 = fmaf(z[4*q + 2], er[4*q + 2], p2);
                        p3 = fmaf(z[4*q + 3], er[4*q + 3], p3);
                    }
                    float dot = __fadd_rn(__fadd_rn(p0, p1), __fadd_rn(p2, p3));
                    float se  = __fsub_rn(s_hn[ci], dot);
                    if (se < be || (se == be && ci < bw)) { be = se; bw = ci; }
                }
            }
        }
    }
    const int win = bw;

    // ---- outputs ----
    const float4* erow = (const float4*)(emb + (size_t)win * CD);
    float lsum = 0.f;
#pragma unroll
    for (int i = 0; i < CD / 4; i++) {
        float4 ev = erow[i];
        float x0 = z[4*i], x1 = z[4*i+1], x2 = z[4*i+2], x3 = z[4*i+3];
        size_t base = ((size_t)b * CD + 4 * i) * HWDIM + hw;
        out[base]             = x0 + (ev.x - x0);
        out[base + HWDIM]     = x1 + (ev.y - x1);
        out[base + 2 * HWDIM] = x2 + (ev.z - x2);
        out[base + 3 * HWDIM] = x3 + (ev.w - x3);
        float e0 = x0 - ev.x, e1 = x1 - ev.y, e2 = x2 - ev.z, e3 = x3 - ev.w;
        lsum += e0 * e0 + e1 * e1 + e2 * e2 + e3 * e3;
    }
#pragma unroll
    for (int off = 16; off > 0; off >>= 1)
        lsum += __shfl_down_sync(0xffffffffu, lsum, off);
    if (l == 0) s_red[w] = lsum;
    __syncthreads();
    if (tid < 8) {
        float v = s_red[tid];
#pragma unroll
        for (int off = 4; off > 0; off >>= 1)
            v += __shfl_down_sync(0x000000ffu, v, off);
        if (tid == 0) {
            atomicAdd(&g_loss, v);
            __threadfence();
            int ticket = atomicAdd(&g_done, 1);
            if (ticket == (int)gridDim.x - 1) {   // last CTA finalizes loss
                if (out_size > LOSS_OFF)
                    out[LOSS_OFF] = 1.25f * (*(volatile float*)&g_loss) * (1.0f / 8388608.0f);
                g_done = 0;                        // reset for next replay
            }
        }
    }
    if (IDX_OFF + pixel < out_size) out[IDX_OFF + pixel] = (float)win;
}

extern "C" void kernel_launch(void* const* d_in, const int* in_sizes, int n_in,
                              void* d_out, int out_size) {
    const float* x   = (const float*)d_in[0];
    const float* emb = (const float*)d_in[1];
    float* out = (float*)d_out;

    vq_prep<<<16, 256>>>(emb);
    vq_mma<<<NPIX / TPB, TPB>>>(x, emb, out, out_size);
}

// round 12
// speedup vs baseline: 3.3459x; 3.3459x over previous
#include <cuda_runtime.h>
#include <cuda_fp16.h>
#include <cstdint>
#include <cstring>

#define KCODES 1024
#define CD     64
#define NPIX   131072
#define HWDIM  4096
#define TPB    256
#define LOSS_OFF 8388608
#define IDX_OFF  8388609
#define NCHUNK 16            // 16 chunks x 64 codes
#define TPC    8             // tiles (of 8 codes) per chunk
#define EPS    0.30f
#define NCAND  12
#define SOFF   128.0f        // score offset making packed keys positive

__device__ float g_halfnorm[KCODES];
__device__ float g_loss;
__device__ int   g_done = 0;
// fragment-ordered fp16 codebook: [tile(128)][lane(32)][2 x uint4]
__device__ __align__(16) uint4 g_Bh[128 * 32 * 2];

static __device__ __forceinline__ uint32_t smem_u32(const void* p) {
    uint32_t a;
    asm("{ .reg .u64 t; cvta.to.shared.u64 t, %1; cvt.u32.u64 %0, t; }" : "=r"(a) : "l"(p));
    return a;
}
static __device__ __forceinline__ void cp_async16(uint32_t s, const void* g) {
    asm volatile("cp.async.ca.shared.global [%0], [%1], 16;" :: "r"(s), "l"(g) : "memory");
}
static __device__ __forceinline__ uint32_t hpack(float a, float b) {
    __half2 h = __floats2half2_rn(a, b);
    uint32_t u; memcpy(&u, &h, 4); return u;
}

#define MMA(d, a, bx, by)                                                          \
    asm volatile("mma.sync.aligned.m16n8k16.row.col.f32.f16.f16.f32 "              \
        "{%0,%1,%2,%3},{%4,%5,%6,%7},{%8,%9},{%0,%1,%2,%3};"                       \
        : "+f"(d[0]), "+f"(d[1]), "+f"(d[2]), "+f"(d[3])                           \
        : "r"(a[0]), "r"(a[1]), "r"(a[2]), "r"(a[3]), "r"(bx), "r"(by))

// exact running top-2 per (slot, chunk): 4 ALU ops per score
#define PM2(p, v, n)                                                               \
    { uint32_t _k = (__float_as_uint(v) & 0xFFFFFC00u) | (uint32_t)(n);            \
      uint32_t _b = max(cm1[p], _k);                                               \
      cm1[p] = min(cm1[p], _k);                                                    \
      cm2[p] = min(cm2[p], _b); }

// branch-free insert into sorted-3 (2x per chunk per slot)
#define INS3(p, kin)                                                               \
    { uint32_t _a, _b = (kin);                                                     \
      _a = min(t1[p], _b); _b = max(t1[p], _b); t1[p] = _a;                        \
      _a = min(t2[p], _b); _b = max(t2[p], _b); t2[p] = _a;                        \
      t3[p] = min(t3[p], _b); }

// ---- prep: halfnorms (R1-replica arithmetic) + fragment-ordered fp16 codebook --
__global__ void vq_prep(const float* __restrict__ emb) {
    int t = blockIdx.x * blockDim.x + threadIdx.x;   // 4096 threads
    if (t == 0) g_loss = 0.f;
    if (t < KCODES) {
        const float4* row = (const float4*)(emb + (size_t)t * CD);
        float s = 0.f;
#pragma unroll
        for (int i = 0; i < CD / 4; i++) {
            float4 v = row[i];
            s += v.x * v.x + v.y * v.y + v.z * v.z + v.w * v.w;
        }
        g_halfnorm[t] = 0.5f * s;
    }
    int tile = t >> 5, l = t & 31, m = l & 3;
    int code = tile * 8 + (l >> 2);
    const float* e = emb + (size_t)code * CD;
    uint32_t h[8];
#pragma unroll
    for (int s = 0; s < 4; s++) {
        int c0 = 16 * s + 2 * m;
        h[2 * s]     = hpack(e[c0],     e[c0 + 1]);
        h[2 * s + 1] = hpack(e[c0 + 8], e[c0 + 9]);
    }
    int base = (tile * 32 + l) * 2;
    g_Bh[base]     = make_uint4(h[0], h[1], h[2], h[3]);
    g_Bh[base + 1] = make_uint4(h[4], h[5], h[6], h[7]);
}

// ---- main: fp16 HMMA screen + chunk-top2/lane-top3 keys + exact rescue ----
__global__ __launch_bounds__(TPB, 2)
void vq_mma(const float* __restrict__ x, const float* __restrict__ emb,
            float* __restrict__ out, int out_size)
{
    // 32 KB pool: B double-buffer (2 x 8 KB) during loop; candidate keys after
    __shared__ __align__(16) unsigned char s_pool[32768];
    __shared__ float s_hn[KCODES];      // exact (rescue comparator)
    __shared__ float s_hnOff[KCODES];   // hn + SOFF (accumulator init)
    __shared__ float s_red[8];

    const int tid = threadIdx.x;
    const int w = tid >> 5, l = tid & 31, g = l >> 2, m = l & 3;
    const int blockpix = blockIdx.x << 8;
    const int b = blockpix >> 12;
    const int hwbase = (blockpix & (HWDIM - 1)) + (w << 5);
    const float* xb = x + (size_t)b * CD * HWDIM;

    // ---- build A fragments (negated z, fp16) ----
    uint32_t ah[2][4][4];
#pragma unroll
    for (int ri = 0; ri < 4; ri++) {
        const int mt = ri >> 1, rr = ri & 1;
        const float* xp = xb + hwbase + g + rr * 8 + mt * 16;
#pragma unroll
        for (int s = 0; s < 4; s++) {
            int c0 = 16 * s + 2 * m;
            float f0 = -__ldg(xp + (size_t)c0 * HWDIM);
            float f1 = -__ldg(xp + (size_t)(c0 + 1) * HWDIM);
            float f2 = -__ldg(xp + (size_t)(c0 + 8) * HWDIM);
            float f3 = -__ldg(xp + (size_t)(c0 + 9) * HWDIM);
            ah[mt][s][rr]     = hpack(f0, f1);
            ah[mt][s][2 + rr] = hpack(f2, f3);
        }
    }

    // halfnorms to smem (exact + offset copy)
#pragma unroll
    for (int i = 0; i < 4; i++) {
        float h = g_halfnorm[tid + i * TPB];
        s_hn[tid + i * TPB]    = h;
        s_hnOff[tid + i * TPB] = h + SOFF;
    }

    // prefetch chunk 0 (8 KB: 2 uint4 per thread)
    {
        uint32_t dh = smem_u32(s_pool) + tid * 32;
        const uint4* sh = g_Bh + tid * 2;
        cp_async16(dh, sh); cp_async16(dh + 16, sh + 1);
        asm volatile("cp.async.commit_group;" ::: "memory");
    }
    asm volatile("cp.async.wait_group 0;" ::: "memory");
    __syncthreads();

    uint32_t t1[4] = {0xFFFFFFFFu,0xFFFFFFFFu,0xFFFFFFFFu,0xFFFFFFFFu};
    uint32_t t2[4] = {0xFFFFFFFFu,0xFFFFFFFFu,0xFFFFFFFFu,0xFFFFFFFFu};
    uint32_t t3[4] = {0xFFFFFFFFu,0xFFFFFFFFu,0xFFFFFFFFu,0xFFFFFFFFu};

#pragma unroll 1
    for (int ch = 0; ch < NCHUNK; ch++) {
        const int buf = ch & 1;
        if (ch + 1 < NCHUNK) {   // async prefetch next chunk
            uint32_t dh = smem_u32(s_pool) + (buf ^ 1) * 8192 + tid * 32;
            const uint4* sh = g_Bh + (ch + 1) * 512 + tid * 2;
            cp_async16(dh, sh); cp_async16(dh + 16, sh + 1);
            asm volatile("cp.async.commit_group;" ::: "memory");
        }

        // exact running top-2 keys per slot for this chunk (16 codes/slot)
        uint32_t cm1[4] = {0xFFFFFFFFu,0xFFFFFFFFu,0xFFFFFFFFu,0xFFFFFFFFu};
        uint32_t cm2[4] = {0xFFFFFFFFu,0xFFFFFFFFu,0xFFFFFFFFu,0xFFFFFFFFu};

        const uint4* bhp = (const uint4*)(s_pool + buf * 8192);
#pragma unroll
        for (int t = 0; t < TPC; t++) {
            uint4 h0 = bhp[t * 64 + l * 2];
            uint4 h1 = bhp[t * 64 + l * 2 + 1];
            const int n0 = ch * 64 + t * 8 + 2 * m;
            float2 hp = *(const float2*)&s_hnOff[n0];

            float d0[4], d1[4];
            d0[0] = hp.x; d0[1] = hp.y; d0[2] = hp.x; d0[3] = hp.y;
            d1[0] = hp.x; d1[1] = hp.y; d1[2] = hp.x; d1[3] = hp.y;

            MMA(d0, ah[0][0], h0.x, h0.y); MMA(d1, ah[1][0], h0.x, h0.y);
            MMA(d0, ah[0][1], h0.z, h0.w); MMA(d1, ah[1][1], h0.z, h0.w);
            MMA(d0, ah[0][2], h1.x, h1.y); MMA(d1, ah[1][2], h1.x, h1.y);
            MMA(d0, ah[0][3], h1.z, h1.w); MMA(d1, ah[1][3], h1.z, h1.w);

            PM2(0, d0[0], n0); PM2(0, d0[1], n0 + 1);
            PM2(1, d0[2], n0); PM2(1, d0[3], n0 + 1);
            PM2(2, d1[0], n0); PM2(2, d1[1], n0 + 1);
            PM2(3, d1[2], n0); PM2(3, d1[3], n0 + 1);
        }
        // fold this chunk's exact top-2 per slot into the lane's top-3
#pragma unroll
        for (int p = 0; p < 4; p++) { INS3(p, cm1[p]); INS3(p, cm2[p]); }

        asm volatile("cp.async.wait_group 0;" ::: "memory");
        __syncthreads();
    }

    // ---- dump all 12 per-pixel candidate keys (4 lanes x top-3) ----
    uint32_t (*s_keys)[NCAND] = (uint32_t(*)[NCAND])s_pool;   // 12 KB
#pragma unroll
    for (int p = 0; p < 4; p++) {
        int row = g + (p & 1) * 8 + (p >> 1) * 16;
        int pr = w * 32 + row;
        s_keys[pr][3 * m]     = t1[p];
        s_keys[pr][3 * m + 1] = t2[p];
        s_keys[pr][3 * m + 2] = t3[p];
    }
    __syncthreads();

    // ---- per-pixel selection + exact R1-replica rescue ----
    const int pixel = blockpix + tid;
    const int hw = pixel & (HWDIM - 1);
    const float* xp = xb + hw;
    float z[CD];
#pragma unroll
    for (int c = 0; c < CD; c++) z[c] = __ldg(xp + (size_t)c * HWDIM);

    uint32_t key[NCAND];
#pragma unroll
    for (int i = 0; i < NCAND; i++) key[i] = s_keys[tid][i];

    uint32_t kmin = key[0];
#pragma unroll
    for (int i = 1; i < NCAND; i++) kmin = min(kmin, key[i]);
    int win = kmin & 1023;
    float smin = __uint_as_float(kmin & 0xFFFFFC00u);

    int nq = 0;
#pragma unroll
    for (int i = 0; i < NCAND; i++)
        nq += (__uint_as_float(key[i] & 0xFFFFFC00u) <= smin + EPS);
    if (nq > 1) {
        // exact rescoring: 4 independent fma chains over c%4, merged
        // (p0+p1)+(p2+p3); score = hn - dot  (R1-replica, known-good)
        float be = 3.4e38f; int bw = 0x7fffffff;
#pragma unroll 1
        for (int i = 0; i < NCAND; i++) {
            if (__uint_as_float(key[i] & 0xFFFFFC00u) <= smin + EPS) {
                int ci = key[i] & 1023;
                const float* er = emb + (size_t)ci * CD;
                float p0 = 0.f, p1 = 0.f, p2 = 0.f, p3 = 0.f;
#pragma unroll
                for (int q = 0; q < CD / 4; q++) {
                    p0 = fmaf(z[4*q],     er[4*q],     p0);
                    p1 = fmaf(z[4*q + 1], er[4*q + 1], p1);
                    p2 = fmaf(z[4*q + 2], er[4*q + 2], p2);
                    p3 = fmaf(z[4*q + 3], er[4*q + 3], p3);
                }
                float dot = __fadd_rn(__fadd_rn(p0, p1), __fadd_rn(p2, p3));
                float se  = __fsub_rn(s_hn[ci], dot);
                if (se < be || (se == be && ci < bw)) { be = se; bw = ci; }
            }
        }
        win = bw;
    }

    // ---- outputs ----
    const float4* erow = (const float4*)(emb + (size_t)win * CD);
    float lsum = 0.f;
#pragma unroll
    for (int i = 0; i < CD / 4; i++) {
        float4 ev = erow[i];
        float x0 = z[4*i], x1 = z[4*i+1], x2 = z[4*i+2], x3 = z[4*i+3];
        size_t base = ((size_t)b * CD + 4 * i) * HWDIM + hw;
        out[base]             = x0 + (ev.x - x0);
        out[base + HWDIM]     = x1 + (ev.y - x1);
        out[base + 2 * HWDIM] = x2 + (ev.z - x2);
        out[base + 3 * HWDIM] = x3 + (ev.w - x3);
        float e0 = x0 - ev.x, e1 = x1 - ev.y, e2 = x2 - ev.z, e3 = x3 - ev.w;
        lsum += e0 * e0 + e1 * e1 + e2 * e2 + e3 * e3;
    }
#pragma unroll
    for (int off = 16; off > 0; off >>= 1)
        lsum += __shfl_down_sync(0xffffffffu, lsum, off);
    if (l == 0) s_red[w] = lsum;
    __syncthreads();
    if (tid < 8) {
        float v = s_red[tid];
#pragma unroll
        for (int off = 4; off > 0; off >>= 1)
            v += __shfl_down_sync(0x000000ffu, v, off);
        if (tid == 0) {
            atomicAdd(&g_loss, v);
            __threadfence();
            int ticket = atomicAdd(&g_done, 1);
            if (ticket == (int)gridDim.x - 1) {   // last CTA finalizes loss
                if (out_size > LOSS_OFF)
                    out[LOSS_OFF] = 1.25f * (*(volatile float*)&g_loss) * (1.0f / 8388608.0f);
                g_done = 0;                        // reset for next replay
            }
        }
    }
    if (IDX_OFF + pixel < out_size) out[IDX_OFF + pixel] = (float)win;
}

extern "C" void kernel_launch(void* const* d_in, const int* in_sizes, int n_in,
                              void* d_out, int out_size) {
    const float* x   = (const float*)d_in[0];
    const float* emb = (const float*)d_in[1];
    float* out = (float*)d_out;

    vq_prep<<<16, 256>>>(emb);
    vq_mma<<<NPIX / TPB, TPB>>>(x, emb, out, out_size);
}